// round 15
// baseline (speedup 1.0000x reference)
#include <cuda_runtime.h>
#include <cuda_bf16.h>
#include <cstdint>

// ---------------------------------------------------------------------------
// PlanStructuredNetwork via mma.sync bf16 (fp32 acc), bf16x3 split.
// R15 = R14 (frag-LDG weights, 2465us winner) + THREE 256-thread groups
// (768 threads/CTA). R14 cut smem 211->88 KB; the RF (not smem) then capped
// occupancy at 512 thr x 128 regs. At 768 thr ptxas caps regs ~80 — the
// GEMM loop needs ~60 — so we trade epilogue temps for +50% warps/SM.
//   Leaf:  (B*1024, 32) -> 128 -> 128 -> 32
//   Join x10: (B*n, 96) -> 128 -> 128 -> 32,  n = 512..1
// ---------------------------------------------------------------------------

#define NB    2048
#define NLEAF 1024
#define FD    32
#define HD    128
#define OD    32

#define TILE_R  32          // per-group tile
#define NGROUPS 3
#define GTHREADS 256
#define THREADS (NGROUPS * GTHREADS)   // 768

__device__ float g_bufA[(size_t)NB * NLEAF * OD];        // 268 MB
__device__ float g_bufB[(size_t)NB * (NLEAF / 2) * OD];  // 134 MB

// Frag arrays: layout ((g * NK + kk) * 2 + hl) * 32 + lane, uint4 per lane.
__device__ uint4 g_fragL1[8 * 2 * 2 * 32];   // leaf W1:  K=32  -> NK=2
__device__ uint4 g_fragL2[8 * 8 * 2 * 32];   // leaf W2:  K=128 -> NK=8
__device__ uint4 g_fragJ1[8 * 6 * 2 * 32];   // join W1:  K=96  -> NK=6
__device__ uint4 g_fragJ2[8 * 8 * 2 * 32];   // join W2:  K=128 -> NK=8

// --- smem byte offsets ---
// Per-group act buffers: X(hi,lo) + H(hi,lo), 32 rows x 272 B each plane.
#define GRP_STRIDE 34816
#define X_HI_OFF 0
#define X_LO_OFF 8704
#define H_HI_OFF 17408
#define H_LO_OFF 26112
// After 3 groups (104448): W3 [32][272] hi/lo + biases
#define W3T_HI  104448
#define W3T_LO  113152
#define B1OFF   121856
#define B2OFF   122368
#define B3OFF   122880
#define SMEM_TOTAL 123136

#define AST     272
#define W3ST    272

// ---------------------------------------------------------------------------
__device__ __forceinline__ uint32_t smem_u32(const void* p) {
    uint32_t a;
    asm("{ .reg .u64 t; cvta.to.shared.u64 t, %1; cvt.u32.u64 %0, t; }"
        : "=r"(a) : "l"(p));
    return a;
}

#define BAR_GRP(id) \
    asm volatile("bar.sync %0, %1;" :: "r"(id), "n"(GTHREADS) : "memory")

#define LDSM_X4(r0, r1, r2, r3, addr)                                          \
    asm volatile("ldmatrix.sync.aligned.m8n8.x4.shared.b16 {%0,%1,%2,%3}, [%4];" \
                 : "=r"(r0), "=r"(r1), "=r"(r2), "=r"(r3) : "r"(addr))

#define LDSM_X2(r0, r1, addr)                                                  \
    asm volatile("ldmatrix.sync.aligned.m8n8.x2.shared.b16 {%0,%1}, [%2];"     \
                 : "=r"(r0), "=r"(r1) : "r"(addr))

#define MMA_BF16(c, a0, a1, a2, a3, b0, b1)                                    \
    asm volatile("mma.sync.aligned.m16n8k16.row.col.f32.bf16.bf16.f32 "        \
                 "{%0,%1,%2,%3}, {%4,%5,%6,%7}, {%8,%9}, {%0,%1,%2,%3};"       \
                 : "+f"((c)[0]), "+f"((c)[1]), "+f"((c)[2]), "+f"((c)[3])      \
                 : "r"(a0), "r"(a1), "r"(a2), "r"(a3), "r"(b0), "r"(b1))

__device__ __forceinline__ void split2(float v0, float v1, uint32_t& hi, uint32_t& lo) {
    __nv_bfloat16 h0 = __float2bfloat16(v0);
    __nv_bfloat16 h1 = __float2bfloat16(v1);
    float r0 = v0 - __bfloat162float(h0);
    float r1 = v1 - __bfloat162float(h1);
    __nv_bfloat16 l0 = __float2bfloat16(r0);
    __nv_bfloat16 l1 = __float2bfloat16(r1);
    hi = (uint32_t)__bfloat16_as_ushort(h0) | ((uint32_t)__bfloat16_as_ushort(h1) << 16);
    lo = (uint32_t)__bfloat16_as_ushort(l0) | ((uint32_t)__bfloat16_as_ushort(l1) << 16);
}

// ---------------------------------------------------------------------------
// Prep: W [Ktot][128] fp32 row-major -> frag array (verified bit-identical).
// ---------------------------------------------------------------------------
__global__ void prep_frags(const float* __restrict__ W, uint4* __restrict__ frag,
                           int Ktot) {
    const int NK = Ktot / 16;
    int idx = blockIdx.x * blockDim.x + threadIdx.x;
    int total = 8 * NK * 32;
    if (idx >= total) return;
    int lane = idx & 31;
    int kk = (idx >> 5) % NK;
    int g = idx / (32 * NK);
    int n0 = g * 16 + (lane >> 2);
    int k0 = kk * 16 + 2 * (lane & 3);

    uint4 hi4, lo4;
    split2(W[k0 * HD + n0],           W[(k0 + 1) * HD + n0],           hi4.x, lo4.x);
    split2(W[(k0 + 8) * HD + n0],     W[(k0 + 9) * HD + n0],           hi4.y, lo4.y);
    split2(W[k0 * HD + n0 + 8],       W[(k0 + 1) * HD + n0 + 8],       hi4.z, lo4.z);
    split2(W[(k0 + 8) * HD + n0 + 8], W[(k0 + 9) * HD + n0 + 8],       hi4.w, lo4.w);

    int base = ((g * NK + kk) * 2) * 32 + lane;
    frag[base] = hi4;
    frag[base + 32] = lo4;
}

// ---------------------------------------------------------------------------
// L1/L2 GEMM: A via LDSM from act smem; B via LDG.128 from frag array.
// ---------------------------------------------------------------------------
template <int NT2, int NK>
__device__ __forceinline__ void gemm3_frag(uint32_t sb,
                                           uint32_t aHiOff, uint32_t aLoOff,
                                           const uint4* __restrict__ frag,
                                           int colBase, int lane, int wm,
                                           float c[][4]) {
#pragma unroll
    for (int j = 0; j < 2 * NT2; j++)
#pragma unroll
        for (int q = 0; q < 4; q++) c[j][q] = 0.f;

    const int aRow = wm * 16 + (lane & 15);
    const uint32_t aKb = (uint32_t)(lane >> 4) * 16;
    const uint32_t aHi = sb + aHiOff + (uint32_t)aRow * AST + aKb;
    const uint32_t aLo = sb + aLoOff + (uint32_t)aRow * AST + aKb;

    const uint4* fb = frag + (size_t)(colBase >> 4) * NK * 64 + lane;

#pragma unroll
    for (int k = 0; k < NK; k++) {
        uint32_t ah0, ah1, ah2, ah3, al0, al1, al2, al3;
        LDSM_X4(ah0, ah1, ah2, ah3, aHi + k * 32);
        LDSM_X4(al0, al1, al2, al3, aLo + k * 32);
#pragma unroll
        for (int j = 0; j < NT2; j++) {
            const uint4* p = fb + (j * NK + k) * 64;
            uint4 bh = __ldg(p);
            uint4 bl = __ldg(p + 32);
            MMA_BF16(c[2 * j],     ah0, ah1, ah2, ah3, bh.x, bh.y);
            MMA_BF16(c[2 * j + 1], ah0, ah1, ah2, ah3, bh.z, bh.w);
            MMA_BF16(c[2 * j],     ah0, ah1, ah2, ah3, bl.x, bl.y);
            MMA_BF16(c[2 * j + 1], ah0, ah1, ah2, ah3, bl.z, bl.w);
            MMA_BF16(c[2 * j],     al0, al1, al2, al3, bh.x, bh.y);
            MMA_BF16(c[2 * j + 1], al0, al1, al2, al3, bh.z, bh.w);
        }
    }
}

// L3 GEMM — smem path: warp = 16 rows x 8 cols via x2 B loads.
template <int NT, int NK>
__device__ __forceinline__ void gemm3_x2(uint32_t sb,
                                         uint32_t aHiOff, uint32_t aLoOff, int astB,
                                         uint32_t bHiOff, uint32_t bLoOff, int bstB,
                                         int colBase, int lane, int wm,
                                         float c[][4]) {
#pragma unroll
    for (int j = 0; j < NT; j++)
#pragma unroll
        for (int q = 0; q < 4; q++) c[j][q] = 0.f;

    const int aRow = wm * 16 + (lane & 15);
    const uint32_t aKb = (uint32_t)(lane >> 4) * 16;
    const uint32_t aHi = sb + aHiOff + (uint32_t)aRow * astB + aKb;
    const uint32_t aLo = sb + aLoOff + (uint32_t)aRow * astB + aKb;

    const int l15 = lane & 15;
    const int nIdx = l15 & 7;
    const uint32_t bKb = (uint32_t)(l15 >> 3) * 16;
    const uint32_t bHi = sb + bHiOff + (uint32_t)(colBase + nIdx) * bstB + bKb;
    const uint32_t bLo = sb + bLoOff + (uint32_t)(colBase + nIdx) * bstB + bKb;

#pragma unroll
    for (int k = 0; k < NK; k++) {
        uint32_t ah0, ah1, ah2, ah3, al0, al1, al2, al3;
        LDSM_X4(ah0, ah1, ah2, ah3, aHi + k * 32);
        LDSM_X4(al0, al1, al2, al3, aLo + k * 32);
#pragma unroll
        for (int j = 0; j < NT; j++) {
            uint32_t bh0, bh1, bl0, bl1;
            LDSM_X2(bh0, bh1, bHi + j * 8 * bstB + k * 32);
            LDSM_X2(bl0, bl1, bLo + j * 8 * bstB + k * 32);
            MMA_BF16(c[j], ah0, ah1, ah2, ah3, bh0, bh1);
            MMA_BF16(c[j], ah0, ah1, ah2, ah3, bl0, bl1);
            MMA_BF16(c[j], al0, al1, al2, al3, bh0, bh1);
        }
    }
}

// Epilogue (32 cols per warp): bias + ReLU + split -> act smem (stride 272)
__device__ __forceinline__ void epi128(char* smem, float c[][4],
                                       uint32_t biasOff, uint32_t hiOff, uint32_t loOff,
                                       int lane, int wm, int colBase) {
    int r0 = wm * 16 + (lane >> 2);
#pragma unroll
    for (int t = 0; t < 4; t++) {
        int n0 = colBase + t * 8 + (lane & 3) * 2;
        float2 bb = *(const float2*)(smem + biasOff + n0 * 4);
        {
            float v0 = fmaxf(c[t][0] + bb.x, 0.f);
            float v1 = fmaxf(c[t][1] + bb.y, 0.f);
            uint32_t hi, lo;
            split2(v0, v1, hi, lo);
            uint32_t o = (uint32_t)r0 * AST + (uint32_t)n0 * 2;
            *(uint32_t*)(smem + hiOff + o) = hi;
            *(uint32_t*)(smem + loOff + o) = lo;
        }
        {
            float v0 = fmaxf(c[t][2] + bb.x, 0.f);
            float v1 = fmaxf(c[t][3] + bb.y, 0.f);
            uint32_t hi, lo;
            split2(v0, v1, hi, lo);
            uint32_t o = (uint32_t)(r0 + 8) * AST + (uint32_t)n0 * 2;
            *(uint32_t*)(smem + hiOff + o) = hi;
            *(uint32_t*)(smem + loOff + o) = lo;
        }
    }
}

// ---------------------------------------------------------------------------
// Gather: 32-row tile -> (xHi,xLo), compile-time NTHR for full unroll.
// ---------------------------------------------------------------------------
template <int MODE, int NTHR>
__device__ __forceinline__ void do_gather(char* smem,
                                          const float* __restrict__ in,
                                          const float* __restrict__ prev,
                                          int row0, int logn, int off,
                                          uint32_t xHi, uint32_t xLo,
                                          int tg) {
    if (MODE == 0) {
        const float2* src = (const float2*)(in + (size_t)row0 * FD);
#pragma unroll
        for (int i = tg; i < TILE_R * 16; i += NTHR) {
            int r = i >> 4, cp = i & 15;
            float2 v = src[i];
            uint32_t hi, lo;
            split2(v.x, v.y, hi, lo);
            uint32_t o = (uint32_t)r * AST + (uint32_t)cp * 4;
            *(uint32_t*)(smem + xHi + o) = hi;
            *(uint32_t*)(smem + xLo + o) = lo;
        }
    } else {
        const int n = 1 << logn;
#pragma unroll
        for (int i = tg; i < TILE_R * 48; i += NTHR) {
            int r = i / 48, cp = i - r * 48;
            int gr = row0 + r;
            int b = gr >> logn, ii = gr & (n - 1);
            float2 v;
            if (cp < 16)
                v = *(const float2*)(in + (((size_t)b * (NLEAF - 1) + off + ii) << 5) + cp * 2);
            else
                v = *(const float2*)(prev + (((size_t)(b << (logn + 1)) + 2 * ii) << 5) + (cp * 2 - 32));
            uint32_t hi, lo;
            split2(v.x, v.y, hi, lo);
            uint32_t o = (uint32_t)r * AST + (uint32_t)cp * 4;
            *(uint32_t*)(smem + xHi + o) = hi;
            *(uint32_t*)(smem + xLo + o) = lo;
        }
    }
}

// ---------------------------------------------------------------------------
// MODE: 0 = leaf (in -> bufA), 1 = join A->B, 2 = join B->A
// Three groups of 256 threads run independent tile streams.
// ---------------------------------------------------------------------------
template <int NK1, int MODE>
__global__ void __launch_bounds__(THREADS, 1)
level_kernel(const float* __restrict__ in,
             const float* __restrict__ W3, const float* __restrict__ b1,
             const float* __restrict__ b2, const float* __restrict__ b3,
             int logn, int off, int ntiles) {
    extern __shared__ char smem[];
    uint32_t sb = smem_u32(smem);
    const int tid = threadIdx.x;

    // --- stage W3 (transposed [N][K], hi/lo) + biases ---
    for (int i = tid; i < HD * OD; i += THREADS) {
        int k = i / OD, n = i - k * OD;
        float v = W3[i];
        __nv_bfloat16 h = __float2bfloat16(v);
        __nv_bfloat16 l = __float2bfloat16(v - __bfloat162float(h));
        uint32_t o = (uint32_t)n * W3ST + (uint32_t)k * 2;
        *(__nv_bfloat16*)(smem + W3T_HI + o) = h;
        *(__nv_bfloat16*)(smem + W3T_LO + o) = l;
    }
    if (tid < HD) {
        ((float*)(smem + B1OFF))[tid] = b1[tid];
        ((float*)(smem + B2OFF))[tid] = b2[tid];
    }
    if (tid < OD) ((float*)(smem + B3OFF))[tid] = b3[tid];
    __syncthreads();

    const uint4* frag1 = (MODE == 0) ? g_fragL1 : g_fragJ1;
    const uint4* frag2 = (MODE == 0) ? g_fragL2 : g_fragJ2;

    // --- group decomposition ---
    const int grp = tid >> 8;            // 0..2
    const int gtid = tid & 255;
    const int gwid = gtid >> 5;
    const int lane = tid & 31;
    const int wm = gwid & 1;
    const int wn = gwid >> 1;
    const int barid = grp + 1;           // named barrier ids 1..3

    const uint32_t gbase = (uint32_t)grp * GRP_STRIDE;
    const uint32_t xHi = gbase + X_HI_OFF, xLo = gbase + X_LO_OFF;
    const uint32_t hHi = gbase + H_HI_OFF, hLo = gbase + H_LO_OFF;

    const float* prev = (MODE == 1) ? g_bufA : g_bufB;
    float* dst = (MODE == 0) ? g_bufA : ((MODE == 1) ? g_bufB : g_bufA);
    const int step = NGROUPS * gridDim.x;

    for (int t = NGROUPS * blockIdx.x + grp; t < ntiles; t += step) {
        const int row0 = t * TILE_R;

        do_gather<MODE, GTHREADS>(smem, in, prev, row0, logn, off, xHi, xLo, gtid);
        BAR_GRP(barid);

        // ---- layer 1: X[32 x K1] @ W1 -> H ----
        {
            float c[4][4];
            gemm3_frag<2, NK1>(sb, xHi, xLo, frag1, wn * 32, lane, wm, c);
            epi128(smem, c, B1OFF, hHi, hLo, lane, wm, wn * 32);
        }
        BAR_GRP(barid);

        // ---- layer 2: H[32 x 128] @ W2 -> X (X dead) ----
        {
            float c[4][4];
            gemm3_frag<2, 8>(sb, hHi, hLo, frag2, wn * 32, lane, wm, c);
            epi128(smem, c, B2OFF, xHi, xLo, lane, wm, wn * 32);
        }
        BAR_GRP(barid);

        // ---- layer 3: X[32 x 128] @ W3T(smem) -> gmem fp32 [32 x 32] ----
        {
            float c[1][4];
            gemm3_x2<1, 8>(sb, xHi, xLo, AST, W3T_HI, W3T_LO, W3ST,
                           wn * 8, lane, wm, c);
            int r0 = row0 + wm * 16 + (lane >> 2);
            int n0 = wn * 8 + (lane & 3) * 2;
            float2 bb = *(const float2*)(smem + B3OFF + n0 * 4);
            float2 v0 = make_float2(c[0][0] + bb.x, c[0][1] + bb.y);
            float2 v1 = make_float2(c[0][2] + bb.x, c[0][3] + bb.y);
            *(float2*)(dst + (size_t)r0 * OD + n0) = v0;
            *(float2*)(dst + (size_t)(r0 + 8) * OD + n0) = v1;
        }
        BAR_GRP(barid);
    }
}

// ---------------------------------------------------------------------------
__global__ void extract_kernel(float* __restrict__ out) {
    int b = blockIdx.x * blockDim.x + threadIdx.x;
    if (b < NB) out[b] = g_bufA[(size_t)b * OD];
}

// ---------------------------------------------------------------------------
extern "C" void kernel_launch(void* const* d_in, const int* in_sizes, int n_in,
                              void* d_out, int out_size) {
    const float* leaf_feats = (const float*)d_in[0];
    const float* internal   = (const float*)d_in[1];
    const float* sW1 = (const float*)d_in[2];
    const float* sb1 = (const float*)d_in[3];
    const float* sW2 = (const float*)d_in[4];
    const float* sb2 = (const float*)d_in[5];
    const float* sW3 = (const float*)d_in[6];
    const float* sb3 = (const float*)d_in[7];
    const float* jW1 = (const float*)d_in[8];
    const float* jb1 = (const float*)d_in[9];
    const float* jW2 = (const float*)d_in[10];
    const float* jb2 = (const float*)d_in[11];
    const float* jW3 = (const float*)d_in[12];
    const float* jb3 = (const float*)d_in[13];
    float* out = (float*)d_out;

    cudaFuncSetAttribute(level_kernel<2, 0>, cudaFuncAttributeMaxDynamicSharedMemorySize, SMEM_TOTAL);
    cudaFuncSetAttribute(level_kernel<6, 1>, cudaFuncAttributeMaxDynamicSharedMemorySize, SMEM_TOTAL);
    cudaFuncSetAttribute(level_kernel<6, 2>, cudaFuncAttributeMaxDynamicSharedMemorySize, SMEM_TOTAL);

    // --- frag prep (runs each replay; idempotent, graph-capturable) ---
    uint4* fL1; cudaGetSymbolAddress((void**)&fL1, g_fragL1);
    uint4* fL2; cudaGetSymbolAddress((void**)&fL2, g_fragL2);
    uint4* fJ1; cudaGetSymbolAddress((void**)&fJ1, g_fragJ1);
    uint4* fJ2; cudaGetSymbolAddress((void**)&fJ2, g_fragJ2);
    prep_frags<<<(8 * 2 * 32 + 255) / 256, 256>>>(sW1, fL1, 32);
    prep_frags<<<(8 * 8 * 32 + 255) / 256, 256>>>(sW2, fL2, 128);
    prep_frags<<<(8 * 6 * 32 + 255) / 256, 256>>>(jW1, fJ1, 96);
    prep_frags<<<(8 * 8 * 32 + 255) / 256, 256>>>(jW2, fJ2, 128);

    // Leaf level: K1 = 32, dst = bufA
    {
        int ntiles = (NB * NLEAF) / TILE_R;     // 65536
        int trips = (ntiles + NGROUPS - 1) / NGROUPS;
        int grid = trips < 148 ? trips : 148;
        level_kernel<2, 0><<<grid, THREADS, SMEM_TOTAL>>>(
            leaf_feats, sW3, sb1, sb2, sb3, 0, 0, ntiles);
    }

    // Join levels n = 512..1; alternate A->B / B->A; final lands in bufA
    int off = 0;
    int mode = 1;
    for (int logn = 9; logn >= 0; --logn) {
        int n = 1 << logn;
        int ntiles = (NB * n) / TILE_R;
        int trips = (ntiles + NGROUPS - 1) / NGROUPS;
        int grid = trips < 148 ? trips : 148;
        if (mode == 1)
            level_kernel<6, 1><<<grid, THREADS, SMEM_TOTAL>>>(
                internal, jW3, jb1, jb2, jb3, logn, off, ntiles);
        else
            level_kernel<6, 2><<<grid, THREADS, SMEM_TOTAL>>>(
                internal, jW3, jb1, jb2, jb3, logn, off, ntiles);
        off += n;
        mode = (mode == 1) ? 2 : 1;
    }

    extract_kernel<<<(NB + 255) / 256, 256>>>(out);
}

// round 16
// speedup vs baseline: 1.1288x; 1.1288x over previous
#include <cuda_runtime.h>
#include <cuda_bf16.h>
#include <cstdint>

// ---------------------------------------------------------------------------
// PlanStructuredNetwork via mma.sync bf16 (fp32 acc), bf16x3 split.
// R16 = R14 (frag-LDG weights, 512 thr, 2 groups — 2465us winner) with
// FATTER WARP TILES: each 256-thr group processes 64-row tiles, warp =
// 16 rows x 64 cols (NT2=4, c[8][4]). Halves barrier rate and A-side LDSM
// traffic per MMA; 8 independent accumulator chains per k-chunk.
//   Leaf:  (B*1024, 32) -> 128 -> 128 -> 32
//   Join x10: (B*n, 96) -> 128 -> 128 -> 32,  n = 512..1
// ---------------------------------------------------------------------------

#define NB    2048
#define NLEAF 1024
#define FD    32
#define HD    128
#define OD    32

#define TILE_R  64          // per-group tile (was 32 in R14)
#define NGROUPS 2
#define GTHREADS 256
#define THREADS (NGROUPS * GTHREADS)   // 512

__device__ float g_bufA[(size_t)NB * NLEAF * OD];        // 268 MB
__device__ float g_bufB[(size_t)NB * (NLEAF / 2) * OD];  // 134 MB

// Frag arrays: layout ((g * NK + kk) * 2 + hl) * 32 + lane, uint4 per lane.
__device__ uint4 g_fragL1[8 * 2 * 2 * 32];   // leaf W1:  K=32  -> NK=2
__device__ uint4 g_fragL2[8 * 8 * 2 * 32];   // leaf W2:  K=128 -> NK=8
__device__ uint4 g_fragJ1[8 * 6 * 2 * 32];   // join W1:  K=96  -> NK=6
__device__ uint4 g_fragJ2[8 * 8 * 2 * 32];   // join W2:  K=128 -> NK=8

// --- smem byte offsets ---
// Per-group act buffers: X(hi,lo) + H(hi,lo), 64 rows x 272 B each plane.
#define PLANE   17408                   // 64 * 272
#define GRP_STRIDE (4 * PLANE)          // 69632
#define X_HI_OFF 0
#define X_LO_OFF PLANE
#define H_HI_OFF (2 * PLANE)
#define H_LO_OFF (3 * PLANE)
// After 2 groups (139264): W3 [32][272] hi/lo + biases
#define W3T_HI  139264
#define W3T_LO  147968
#define B1OFF   156672
#define B2OFF   157184
#define B3OFF   157696
#define SMEM_TOTAL 157952

#define AST     272
#define W3ST    272

// ---------------------------------------------------------------------------
__device__ __forceinline__ uint32_t smem_u32(const void* p) {
    uint32_t a;
    asm("{ .reg .u64 t; cvta.to.shared.u64 t, %1; cvt.u32.u64 %0, t; }"
        : "=r"(a) : "l"(p));
    return a;
}

#define BAR_GRP(id) \
    asm volatile("bar.sync %0, %1;" :: "r"(id), "n"(GTHREADS) : "memory")

#define LDSM_X4(r0, r1, r2, r3, addr)                                          \
    asm volatile("ldmatrix.sync.aligned.m8n8.x4.shared.b16 {%0,%1,%2,%3}, [%4];" \
                 : "=r"(r0), "=r"(r1), "=r"(r2), "=r"(r3) : "r"(addr))

#define LDSM_X2(r0, r1, addr)                                                  \
    asm volatile("ldmatrix.sync.aligned.m8n8.x2.shared.b16 {%0,%1}, [%2];"     \
                 : "=r"(r0), "=r"(r1) : "r"(addr))

#define MMA_BF16(c, a0, a1, a2, a3, b0, b1)                                    \
    asm volatile("mma.sync.aligned.m16n8k16.row.col.f32.bf16.bf16.f32 "        \
                 "{%0,%1,%2,%3}, {%4,%5,%6,%7}, {%8,%9}, {%0,%1,%2,%3};"       \
                 : "+f"((c)[0]), "+f"((c)[1]), "+f"((c)[2]), "+f"((c)[3])      \
                 : "r"(a0), "r"(a1), "r"(a2), "r"(a3), "r"(b0), "r"(b1))

__device__ __forceinline__ void split2(float v0, float v1, uint32_t& hi, uint32_t& lo) {
    __nv_bfloat16 h0 = __float2bfloat16(v0);
    __nv_bfloat16 h1 = __float2bfloat16(v1);
    float r0 = v0 - __bfloat162float(h0);
    float r1 = v1 - __bfloat162float(h1);
    __nv_bfloat16 l0 = __float2bfloat16(r0);
    __nv_bfloat16 l1 = __float2bfloat16(r1);
    hi = (uint32_t)__bfloat16_as_ushort(h0) | ((uint32_t)__bfloat16_as_ushort(h1) << 16);
    lo = (uint32_t)__bfloat16_as_ushort(l0) | ((uint32_t)__bfloat16_as_ushort(l1) << 16);
}

// ---------------------------------------------------------------------------
// Prep: W [Ktot][128] fp32 row-major -> frag array (verified bit-identical).
// ---------------------------------------------------------------------------
__global__ void prep_frags(const float* __restrict__ W, uint4* __restrict__ frag,
                           int Ktot) {
    const int NK = Ktot / 16;
    int idx = blockIdx.x * blockDim.x + threadIdx.x;
    int total = 8 * NK * 32;
    if (idx >= total) return;
    int lane = idx & 31;
    int kk = (idx >> 5) % NK;
    int g = idx / (32 * NK);
    int n0 = g * 16 + (lane >> 2);
    int k0 = kk * 16 + 2 * (lane & 3);

    uint4 hi4, lo4;
    split2(W[k0 * HD + n0],           W[(k0 + 1) * HD + n0],           hi4.x, lo4.x);
    split2(W[(k0 + 8) * HD + n0],     W[(k0 + 9) * HD + n0],           hi4.y, lo4.y);
    split2(W[k0 * HD + n0 + 8],       W[(k0 + 1) * HD + n0 + 8],       hi4.z, lo4.z);
    split2(W[(k0 + 8) * HD + n0 + 8], W[(k0 + 9) * HD + n0 + 8],       hi4.w, lo4.w);

    int base = ((g * NK + kk) * 2) * 32 + lane;
    frag[base] = hi4;
    frag[base + 32] = lo4;
}

// ---------------------------------------------------------------------------
// L1/L2 GEMM: A via LDSM (one hi+lo pair per k feeds 6*NT2 MMAs);
// B via LDG.128 from frag array.
// ---------------------------------------------------------------------------
template <int NT2, int NK>
__device__ __forceinline__ void gemm3_frag(uint32_t sb,
                                           uint32_t aHiOff, uint32_t aLoOff,
                                           const uint4* __restrict__ frag,
                                           int colBase, int lane, int wm,
                                           float c[][4]) {
#pragma unroll
    for (int j = 0; j < 2 * NT2; j++)
#pragma unroll
        for (int q = 0; q < 4; q++) c[j][q] = 0.f;

    const int aRow = wm * 16 + (lane & 15);
    const uint32_t aKb = (uint32_t)(lane >> 4) * 16;
    const uint32_t aHi = sb + aHiOff + (uint32_t)aRow * AST + aKb;
    const uint32_t aLo = sb + aLoOff + (uint32_t)aRow * AST + aKb;

    const uint4* fb = frag + (size_t)(colBase >> 4) * NK * 64 + lane;

#pragma unroll
    for (int k = 0; k < NK; k++) {
        uint32_t ah0, ah1, ah2, ah3, al0, al1, al2, al3;
        LDSM_X4(ah0, ah1, ah2, ah3, aHi + k * 32);
        LDSM_X4(al0, al1, al2, al3, aLo + k * 32);
#pragma unroll
        for (int j = 0; j < NT2; j++) {
            const uint4* p = fb + (j * NK + k) * 64;
            uint4 bh = __ldg(p);
            uint4 bl = __ldg(p + 32);
            MMA_BF16(c[2 * j],     ah0, ah1, ah2, ah3, bh.x, bh.y);
            MMA_BF16(c[2 * j + 1], ah0, ah1, ah2, ah3, bh.z, bh.w);
            MMA_BF16(c[2 * j],     ah0, ah1, ah2, ah3, bl.x, bl.y);
            MMA_BF16(c[2 * j + 1], ah0, ah1, ah2, ah3, bl.z, bl.w);
            MMA_BF16(c[2 * j],     al0, al1, al2, al3, bh.x, bh.y);
            MMA_BF16(c[2 * j + 1], al0, al1, al2, al3, bh.z, bh.w);
        }
    }
}

// L3 GEMM — smem path (R4 shape): warp = 16 rows x 16 cols via x2 B loads.
template <int NT, int NK>
__device__ __forceinline__ void gemm3_x2(uint32_t sb,
                                         uint32_t aHiOff, uint32_t aLoOff, int astB,
                                         uint32_t bHiOff, uint32_t bLoOff, int bstB,
                                         int colBase, int lane, int wm,
                                         float c[][4]) {
#pragma unroll
    for (int j = 0; j < NT; j++)
#pragma unroll
        for (int q = 0; q < 4; q++) c[j][q] = 0.f;

    const int aRow = wm * 16 + (lane & 15);
    const uint32_t aKb = (uint32_t)(lane >> 4) * 16;
    const uint32_t aHi = sb + aHiOff + (uint32_t)aRow * astB + aKb;
    const uint32_t aLo = sb + aLoOff + (uint32_t)aRow * astB + aKb;

    const int l15 = lane & 15;
    const int nIdx = l15 & 7;
    const uint32_t bKb = (uint32_t)(l15 >> 3) * 16;
    const uint32_t bHi = sb + bHiOff + (uint32_t)(colBase + nIdx) * bstB + bKb;
    const uint32_t bLo = sb + bLoOff + (uint32_t)(colBase + nIdx) * bstB + bKb;

#pragma unroll
    for (int k = 0; k < NK; k++) {
        uint32_t ah0, ah1, ah2, ah3, al0, al1, al2, al3;
        LDSM_X4(ah0, ah1, ah2, ah3, aHi + k * 32);
        LDSM_X4(al0, al1, al2, al3, aLo + k * 32);
#pragma unroll
        for (int j = 0; j < NT; j++) {
            uint32_t bh0, bh1, bl0, bl1;
            LDSM_X2(bh0, bh1, bHi + j * 8 * bstB + k * 32);
            LDSM_X2(bl0, bl1, bLo + j * 8 * bstB + k * 32);
            MMA_BF16(c[j], ah0, ah1, ah2, ah3, bh0, bh1);
            MMA_BF16(c[j], ah0, ah1, ah2, ah3, bl0, bl1);
            MMA_BF16(c[j], al0, al1, al2, al3, bh0, bh1);
        }
    }
}

// Epilogue (64 cols per warp, NT8 pairs): bias + ReLU + split -> act smem.
template <int NT8>
__device__ __forceinline__ void epiN(char* smem, float c[][4],
                                     uint32_t biasOff, uint32_t hiOff, uint32_t loOff,
                                     int lane, int wm, int colBase) {
    int r0 = wm * 16 + (lane >> 2);
#pragma unroll
    for (int t = 0; t < NT8; t++) {
        int n0 = colBase + t * 8 + (lane & 3) * 2;
        float2 bb = *(const float2*)(smem + biasOff + n0 * 4);
        {
            float v0 = fmaxf(c[t][0] + bb.x, 0.f);
            float v1 = fmaxf(c[t][1] + bb.y, 0.f);
            uint32_t hi, lo;
            split2(v0, v1, hi, lo);
            uint32_t o = (uint32_t)r0 * AST + (uint32_t)n0 * 2;
            *(uint32_t*)(smem + hiOff + o) = hi;
            *(uint32_t*)(smem + loOff + o) = lo;
        }
        {
            float v0 = fmaxf(c[t][2] + bb.x, 0.f);
            float v1 = fmaxf(c[t][3] + bb.y, 0.f);
            uint32_t hi, lo;
            split2(v0, v1, hi, lo);
            uint32_t o = (uint32_t)(r0 + 8) * AST + (uint32_t)n0 * 2;
            *(uint32_t*)(smem + hiOff + o) = hi;
            *(uint32_t*)(smem + loOff + o) = lo;
        }
    }
}

// ---------------------------------------------------------------------------
// Gather: 64-row tile -> (xHi,xLo), compile-time NTHR for full unroll.
// ---------------------------------------------------------------------------
template <int MODE, int NTHR>
__device__ __forceinline__ void do_gather(char* smem,
                                          const float* __restrict__ in,
                                          const float* __restrict__ prev,
                                          int row0, int logn, int off,
                                          uint32_t xHi, uint32_t xLo,
                                          int tg) {
    if (MODE == 0) {
        const float2* src = (const float2*)(in + (size_t)row0 * FD);
#pragma unroll
        for (int i = tg; i < TILE_R * 16; i += NTHR) {
            int r = i >> 4, cp = i & 15;
            float2 v = src[i];
            uint32_t hi, lo;
            split2(v.x, v.y, hi, lo);
            uint32_t o = (uint32_t)r * AST + (uint32_t)cp * 4;
            *(uint32_t*)(smem + xHi + o) = hi;
            *(uint32_t*)(smem + xLo + o) = lo;
        }
    } else {
        const int n = 1 << logn;
#pragma unroll
        for (int i = tg; i < TILE_R * 48; i += NTHR) {
            int r = i / 48, cp = i - r * 48;
            int gr = row0 + r;
            int b = gr >> logn, ii = gr & (n - 1);
            float2 v;
            if (cp < 16)
                v = *(const float2*)(in + (((size_t)b * (NLEAF - 1) + off + ii) << 5) + cp * 2);
            else
                v = *(const float2*)(prev + (((size_t)(b << (logn + 1)) + 2 * ii) << 5) + (cp * 2 - 32));
            uint32_t hi, lo;
            split2(v.x, v.y, hi, lo);
            uint32_t o = (uint32_t)r * AST + (uint32_t)cp * 4;
            *(uint32_t*)(smem + xHi + o) = hi;
            *(uint32_t*)(smem + xLo + o) = lo;
        }
    }
}

// ---------------------------------------------------------------------------
// MODE: 0 = leaf (in -> bufA), 1 = join A->B, 2 = join B->A
// Two groups of 256 threads; each group: 64-row tiles, warp = 16r x 64c.
// ---------------------------------------------------------------------------
template <int NK1, int MODE>
__global__ void __launch_bounds__(THREADS, 1)
level_kernel(const float* __restrict__ in,
             const float* __restrict__ W3, const float* __restrict__ b1,
             const float* __restrict__ b2, const float* __restrict__ b3,
             int logn, int off, int ntiles) {
    extern __shared__ char smem[];
    uint32_t sb = smem_u32(smem);
    const int tid = threadIdx.x;

    // --- stage W3 (transposed [N][K], hi/lo) + biases ---
    for (int i = tid; i < HD * OD; i += THREADS) {
        int k = i / OD, n = i - k * OD;
        float v = W3[i];
        __nv_bfloat16 h = __float2bfloat16(v);
        __nv_bfloat16 l = __float2bfloat16(v - __bfloat162float(h));
        uint32_t o = (uint32_t)n * W3ST + (uint32_t)k * 2;
        *(__nv_bfloat16*)(smem + W3T_HI + o) = h;
        *(__nv_bfloat16*)(smem + W3T_LO + o) = l;
    }
    if (tid < HD) {
        ((float*)(smem + B1OFF))[tid] = b1[tid];
        ((float*)(smem + B2OFF))[tid] = b2[tid];
    }
    if (tid < OD) ((float*)(smem + B3OFF))[tid] = b3[tid];
    __syncthreads();

    const uint4* frag1 = (MODE == 0) ? g_fragL1 : g_fragJ1;
    const uint4* frag2 = (MODE == 0) ? g_fragL2 : g_fragJ2;

    // --- group decomposition: 8 warps = wm(4 row groups) x wn(2 col groups) ---
    const int grp = tid >> 8;            // 0..1
    const int gtid = tid & 255;
    const int gwid = gtid >> 5;
    const int lane = tid & 31;
    const int wm = gwid & 3;             // rows wm*16 .. +16
    const int wn = gwid >> 2;            // cols wn*64 (L1/L2); wn*16 (L3)
    const int barid = grp + 1;

    const uint32_t gbase = (uint32_t)grp * GRP_STRIDE;
    const uint32_t xHi = gbase + X_HI_OFF, xLo = gbase + X_LO_OFF;
    const uint32_t hHi = gbase + H_HI_OFF, hLo = gbase + H_LO_OFF;

    const float* prev = (MODE == 1) ? g_bufA : g_bufB;
    float* dst = (MODE == 0) ? g_bufA : ((MODE == 1) ? g_bufB : g_bufA);
    const int step = NGROUPS * gridDim.x;

    for (int t = NGROUPS * blockIdx.x + grp; t < ntiles; t += step) {
        const int row0 = t * TILE_R;

        do_gather<MODE, GTHREADS>(smem, in, prev, row0, logn, off, xHi, xLo, gtid);
        BAR_GRP(barid);

        // ---- layer 1: X[64 x K1] @ W1 -> H (warp: 16r x 64c) ----
        {
            float c[8][4];
            gemm3_frag<4, NK1>(sb, xHi, xLo, frag1, wn * 64, lane, wm, c);
            epiN<8>(smem, c, B1OFF, hHi, hLo, lane, wm, wn * 64);
        }
        BAR_GRP(barid);

        // ---- layer 2: H[64 x 128] @ W2 -> X (X dead) ----
        {
            float c[8][4];
            gemm3_frag<4, 8>(sb, hHi, hLo, frag2, wn * 64, lane, wm, c);
            epiN<8>(smem, c, B2OFF, xHi, xLo, lane, wm, wn * 64);
        }
        BAR_GRP(barid);

        // ---- layer 3: X[64 x 128] @ W3T(smem) -> gmem fp32 [64 x 32] ----
        {
            float c[2][4];
            gemm3_x2<2, 8>(sb, xHi, xLo, AST, W3T_HI, W3T_LO, W3ST,
                           wn * 16, lane, wm, c);
            int r0 = row0 + wm * 16 + (lane >> 2);
#pragma unroll
            for (int tt = 0; tt < 2; tt++) {
                int n0 = wn * 16 + tt * 8 + (lane & 3) * 2;
                float2 bb = *(const float2*)(smem + B3OFF + n0 * 4);
                float2 v0 = make_float2(c[tt][0] + bb.x, c[tt][1] + bb.y);
                float2 v1 = make_float2(c[tt][2] + bb.x, c[tt][3] + bb.y);
                *(float2*)(dst + (size_t)r0 * OD + n0) = v0;
                *(float2*)(dst + (size_t)(r0 + 8) * OD + n0) = v1;
            }
        }
        BAR_GRP(barid);
    }
}

// ---------------------------------------------------------------------------
__global__ void extract_kernel(float* __restrict__ out) {
    int b = blockIdx.x * blockDim.x + threadIdx.x;
    if (b < NB) out[b] = g_bufA[(size_t)b * OD];
}

// ---------------------------------------------------------------------------
extern "C" void kernel_launch(void* const* d_in, const int* in_sizes, int n_in,
                              void* d_out, int out_size) {
    const float* leaf_feats = (const float*)d_in[0];
    const float* internal   = (const float*)d_in[1];
    const float* sW1 = (const float*)d_in[2];
    const float* sb1 = (const float*)d_in[3];
    const float* sW2 = (const float*)d_in[4];
    const float* sb2 = (const float*)d_in[5];
    const float* sW3 = (const float*)d_in[6];
    const float* sb3 = (const float*)d_in[7];
    const float* jW1 = (const float*)d_in[8];
    const float* jb1 = (const float*)d_in[9];
    const float* jW2 = (const float*)d_in[10];
    const float* jb2 = (const float*)d_in[11];
    const float* jW3 = (const float*)d_in[12];
    const float* jb3 = (const float*)d_in[13];
    float* out = (float*)d_out;

    cudaFuncSetAttribute(level_kernel<2, 0>, cudaFuncAttributeMaxDynamicSharedMemorySize, SMEM_TOTAL);
    cudaFuncSetAttribute(level_kernel<6, 1>, cudaFuncAttributeMaxDynamicSharedMemorySize, SMEM_TOTAL);
    cudaFuncSetAttribute(level_kernel<6, 2>, cudaFuncAttributeMaxDynamicSharedMemorySize, SMEM_TOTAL);

    // --- frag prep (idempotent, graph-capturable) ---
    uint4* fL1; cudaGetSymbolAddress((void**)&fL1, g_fragL1);
    uint4* fL2; cudaGetSymbolAddress((void**)&fL2, g_fragL2);
    uint4* fJ1; cudaGetSymbolAddress((void**)&fJ1, g_fragJ1);
    uint4* fJ2; cudaGetSymbolAddress((void**)&fJ2, g_fragJ2);
    prep_frags<<<(8 * 2 * 32 + 255) / 256, 256>>>(sW1, fL1, 32);
    prep_frags<<<(8 * 8 * 32 + 255) / 256, 256>>>(sW2, fL2, 128);
    prep_frags<<<(8 * 6 * 32 + 255) / 256, 256>>>(jW1, fJ1, 96);
    prep_frags<<<(8 * 8 * 32 + 255) / 256, 256>>>(jW2, fJ2, 128);

    // Leaf level: K1 = 32, dst = bufA
    {
        int ntiles = (NB * NLEAF) / TILE_R;     // 32768
        int trips = (ntiles + NGROUPS - 1) / NGROUPS;
        int grid = trips < 148 ? trips : 148;
        level_kernel<2, 0><<<grid, THREADS, SMEM_TOTAL>>>(
            leaf_feats, sW3, sb1, sb2, sb3, 0, 0, ntiles);
    }

    // Join levels n = 512..1; alternate A->B / B->A; final lands in bufA
    int off = 0;
    int mode = 1;
    for (int logn = 9; logn >= 0; --logn) {
        int n = 1 << logn;
        int ntiles = (NB * n) / TILE_R;
        int trips = (ntiles + NGROUPS - 1) / NGROUPS;
        int grid = trips < 148 ? trips : 148;
        if (mode == 1)
            level_kernel<6, 1><<<grid, THREADS, SMEM_TOTAL>>>(
                internal, jW3, jb1, jb2, jb3, logn, off, ntiles);
        else
            level_kernel<6, 2><<<grid, THREADS, SMEM_TOTAL>>>(
                internal, jW3, jb1, jb2, jb3, logn, off, ntiles);
        off += n;
        mode = (mode == 1) ? 2 : 1;
    }

    extract_kernel<<<(NB + 255) / 256, 256>>>(out);
}